// round 6
// baseline (speedup 1.0000x reference)
#include <cuda_runtime.h>
#include <cuda_fp16.h>
#include <math.h>
#include <stdint.h>

// ---------------------------------------------------------------------------
// Problem constants
// ---------------------------------------------------------------------------
#define Bq   8
#define Tq   1024
#define Dm   1024
#define Hh   16
#define Ll   8
#define Vv   8192
#define HD   64
#define BT   (Bq*Tq)

// ---------------------------------------------------------------------------
// Scratch (static device globals)
// ---------------------------------------------------------------------------
__device__ float g_x[BT * Dm];           // residual stream (f32)
__device__ float g_qkv[3L * BT * Dm];    // q | k | v

__device__ __half g_pa_h[BT * Dm];       // pair buf A: LN out / attn out
__device__ __half g_pa_l[BT * Dm];
__device__ __half g_pb_h[BT * 2 * Dm];   // pair buf B: MLP hidden
__device__ __half g_pb_l[BT * 2 * Dm];

#define DD      (Dm*Dm)
#define OFF_WQ  0L
#define OFF_WK  (8L*DD)
#define OFF_WV  (16L*DD)
#define OFF_WO  (24L*DD)
#define OFF_W1  (32L*DD)
#define OFF_W2  (48L*DD)
#define OFF_HW  (64L*DD)
#define WTOT    (72L*DD)
__device__ __half g_wh[WTOT];
__device__ __half g_wl[WTOT];

// ---------------------------------------------------------------------------
// Helpers
// ---------------------------------------------------------------------------
__device__ __forceinline__ uint32_t smem_u32(const void* p) {
    uint32_t a;
    asm("{ .reg .u64 t; cvta.to.shared.u64 t, %1; cvt.u32.u64 %0, t; }"
        : "=r"(a) : "l"(p));
    return a;
}
__device__ __forceinline__ void cpa16(uint32_t dst, const void* src) {
    asm volatile("cp.async.cg.shared.global [%0], [%1], 16;" :: "r"(dst), "l"(src));
}
__device__ __forceinline__ void ldm_x4(uint32_t& r0, uint32_t& r1,
                                       uint32_t& r2, uint32_t& r3, uint32_t addr) {
    asm volatile("ldmatrix.sync.aligned.m8n8.x4.shared.b16 {%0,%1,%2,%3}, [%4];"
                 : "=r"(r0), "=r"(r1), "=r"(r2), "=r"(r3) : "r"(addr));
}
__device__ __forceinline__ void mma_f16(float& d0, float& d1, float& d2, float& d3,
                                        uint32_t a0, uint32_t a1, uint32_t a2, uint32_t a3,
                                        uint32_t b0, uint32_t b1) {
    asm volatile(
        "mma.sync.aligned.m16n8k16.row.col.f32.f16.f16.f32 "
        "{%0,%1,%2,%3}, {%4,%5,%6,%7}, {%8,%9}, {%0,%1,%2,%3};"
        : "+f"(d0), "+f"(d1), "+f"(d2), "+f"(d3)
        : "r"(a0), "r"(a1), "r"(a2), "r"(a3), "r"(b0), "r"(b1));
}
__device__ __forceinline__ void split16(float x, __half& hi, __half& lo) {
    hi = __float2half_rn(x);
    lo = __float2half_rn(x - __half2float(hi));
}

// ---------------------------------------------------------------------------
// Weight f32 -> f16 hi/lo pair conversion
// ---------------------------------------------------------------------------
__global__ __launch_bounds__(256) void cvt_pair(
    const float* __restrict__ s, __half* __restrict__ h,
    __half* __restrict__ l, long n)
{
    long i = ((long)blockIdx.x * 256 + threadIdx.x) * 4;
    if (i >= n) return;
    float4 v = *(const float4*)(s + i);
    __half h0, h1, h2, h3, l0, l1, l2, l3;
    split16(v.x, h0, l0); split16(v.y, h1, l1);
    split16(v.z, h2, l2); split16(v.w, h3, l3);
    *(__half2*)(h + i)     = __halves2half2(h0, h1);
    *(__half2*)(h + i + 2) = __halves2half2(h2, h3);
    *(__half2*)(l + i)     = __halves2half2(l0, l1);
    *(__half2*)(l + i + 2) = __halves2half2(l2, l3);
}

// ---------------------------------------------------------------------------
// Embedding
// ---------------------------------------------------------------------------
__global__ __launch_bounds__(256) void embed_kernel(
    const int* __restrict__ idx, const int* __restrict__ ts,
    const float* __restrict__ tok, const float* __restrict__ pos,
    const float* __restrict__ gpos, float* __restrict__ x)
{
    long i = (long)blockIdx.x * 256 + threadIdx.x;
    int d = (int)(i % Dm);
    long bt = i / Dm;
    int t = (int)(bt % Tq);
    int b = (int)(bt / Tq);
    int tokid = idx[b * Tq + t];
    int tstep = ts[b];
    x[i] = tok[(long)tokid * Dm + d] + gpos[(long)tstep * Dm + d] + pos[(long)t * Dm + d];
}

// ---------------------------------------------------------------------------
// LayerNorm -> f16 hi/lo pair output
// ---------------------------------------------------------------------------
__global__ __launch_bounds__(256) void layernorm_pair(
    const float* __restrict__ X, const float* __restrict__ w,
    const float* __restrict__ b, __half* __restrict__ Yh, __half* __restrict__ Yl)
{
    int row = blockIdx.x;
    const float* x = X + (long)row * Dm;
    int tid = threadIdx.x;

    int i = tid * 4;
    float4 v = *(const float4*)(x + i);
    float s  = v.x + v.y + v.z + v.w;
    float ss = v.x*v.x + v.y*v.y + v.z*v.z + v.w*v.w;

    __shared__ float rs[8], rss[8];
    #pragma unroll
    for (int m = 16; m; m >>= 1) {
        s  += __shfl_xor_sync(0xffffffffu, s,  m);
        ss += __shfl_xor_sync(0xffffffffu, ss, m);
    }
    int wid = tid >> 5, lane = tid & 31;
    if (lane == 0) { rs[wid] = s; rss[wid] = ss; }
    __syncthreads();
    if (wid == 0) {
        s  = (lane < 8) ? rs[lane]  : 0.f;
        ss = (lane < 8) ? rss[lane] : 0.f;
        #pragma unroll
        for (int m = 4; m; m >>= 1) {
            s  += __shfl_xor_sync(0xffffffffu, s,  m);
            ss += __shfl_xor_sync(0xffffffffu, ss, m);
        }
        if (lane == 0) { rs[0] = s; rss[0] = ss; }
    }
    __syncthreads();
    float mean = rs[0] * (1.0f / Dm);
    float var  = rss[0] * (1.0f / Dm) - mean * mean;
    float rstd = rsqrtf(var + 1e-5f);

    float4 wv = *(const float4*)(w + i);
    float4 bv = *(const float4*)(b + i);
    float o0 = (v.x - mean) * rstd * wv.x + bv.x;
    float o1 = (v.y - mean) * rstd * wv.y + bv.y;
    float o2 = (v.z - mean) * rstd * wv.z + bv.z;
    float o3 = (v.w - mean) * rstd * wv.w + bv.w;

    long base = (long)row * Dm + i;
    __half h0, h1, h2, h3, l0, l1, l2, l3;
    split16(o0, h0, l0); split16(o1, h1, l1);
    split16(o2, h2, l2); split16(o3, h3, l3);
    *(__half2*)(Yh + base)     = __halves2half2(h0, h1);
    *(__half2*)(Yh + base + 2) = __halves2half2(h2, h3);
    *(__half2*)(Yl + base)     = __halves2half2(l0, l1);
    *(__half2*)(Yl + base + 2) = __halves2half2(l2, l3);
}

// ---------------------------------------------------------------------------
// HMMA GEMM v2 (3x f16 split): CTA tile 256x128 (MxN), k-step 32,
// 3-stage cp.async pipeline, 8 warps (4m x 2n), warp tile 64x64.
// Epilogues: NONE / ADD residual / GELU->pair / QKV fused.
// smem per stage: Ah(256x40h) Al Bh(128x40h) Bl = 61440 B; 3 stages = 180 KB.
// ---------------------------------------------------------------------------
#define EPI_NONE 0
#define EPI_ADD  1
#define EPI_GELU 2
#define EPI_QKV  3

#define PK        40
#define A_TILE_H  (256*PK)            // 10240 halfs
#define B_TILE_H  (128*PK)            // 5120 halfs
#define STG_H     (2*A_TILE_H + 2*B_TILE_H)   // 30720 halfs
#define GEMM_SMEM (3*STG_H*2)         // 184320 B

template<int EPI>
__global__ __launch_bounds__(256, 1) void gemm_hmma(
    const __half* __restrict__ Ah, const __half* __restrict__ Al,
    const __half* __restrict__ Bh, const __half* __restrict__ Bl,
    long bStride,
    const float* __restrict__ b0p, const float* __restrict__ b1p,
    const float* __restrict__ b2p, const float* __restrict__ res,
    float* __restrict__ C, __half* __restrict__ Ch, __half* __restrict__ Cl,
    int M, int N, int K)
{
    extern __shared__ __align__(16) __half gsm[];
    const uint32_t sbase = smem_u32(gsm);

    const int tid = threadIdx.x, lane = tid & 31, warp = tid >> 5;
    const int g = lane >> 2, t = lane & 3, l7 = lane & 7;
    const int wm = warp >> 1, wn = warp & 1;
    const int m0 = blockIdx.y * 256, n0 = blockIdx.x * 128;

    float acc[4][8][4];
    #pragma unroll
    for (int a = 0; a < 4; a++)
        #pragma unroll
        for (int b = 0; b < 8; b++)
            #pragma unroll
            for (int c = 0; c < 4; c++) acc[a][b][c] = 0.f;

    const int S = K >> 5;

    // 3072 16B-chunks per stage: Ah[0,1024) Al[1024,2048) Bh[2048,2560) Bl[2560,3072)
    auto issue = [&](int k0, int buf) {
        #pragma unroll
        for (int j = 0; j < 12; j++) {
            int c = tid + 256 * j;
            const __half* src;
            uint32_t dstoff;
            if (c < 2048) {
                int hilo = c >> 10;
                int r = (c >> 2) & 255;
                int q = c & 3;
                src = (hilo ? Al : Ah) + (long)(m0 + r) * K + k0 + q * 8;
                dstoff = (uint32_t)(buf * STG_H + hilo * A_TILE_H + r * PK + q * 8);
            } else {
                int c2 = c - 2048;
                int hilo = c2 >> 9;
                int r = (c2 >> 2) & 127;
                int q = c2 & 3;
                long roff;
                if (EPI == EPI_QKV) {
                    int rg = n0 + r;
                    roff = (long)(rg >> 10) * bStride + (long)(rg & 1023) * K;
                } else {
                    roff = (long)(n0 + r) * K;
                }
                src = (hilo ? Bl : Bh) + roff + k0 + q * 8;
                dstoff = (uint32_t)(buf * STG_H + 2 * A_TILE_H + hilo * B_TILE_H + r * PK + q * 8);
            }
            cpa16(sbase + dstoff * 2u, src);
        }
        asm volatile("cp.async.commit_group;" ::: "memory");
    };

    issue(0, 0);
    if (S > 1) issue(32, 1);

    for (int s = 0; s < S; s++) {
        if (s < S - 1) asm volatile("cp.async.wait_group 1;" ::: "memory");
        else           asm volatile("cp.async.wait_group 0;" ::: "memory");
        __syncthreads();
        if (s + 2 < S) issue((s + 2) << 5, (s + 2) % 3);

        uint32_t sb  = sbase + (uint32_t)((s % 3) * STG_H) * 2u;
        uint32_t A_h = sb;
        uint32_t A_l = sb + A_TILE_H * 2u;
        uint32_t B_h = sb + 2u * A_TILE_H * 2u;
        uint32_t B_l = B_h + B_TILE_H * 2u;

        #pragma unroll
        for (int kk = 0; kk < 32; kk += 16) {
            uint32_t bh[8][2], bl[8][2];
            #pragma unroll
            for (int p = 0; p < 4; p++) {
                int row = wn * 64 + p * 16 + l7 + ((lane & 16) >> 1);
                int kc  = kk + (lane & 8);
                uint32_t off = (uint32_t)(row * PK + kc) * 2u;
                ldm_x4(bh[2*p][0], bh[2*p][1], bh[2*p+1][0], bh[2*p+1][1], B_h + off);
                ldm_x4(bl[2*p][0], bl[2*p][1], bl[2*p+1][0], bl[2*p+1][1], B_l + off);
            }
            #pragma unroll
            for (int mi = 0; mi < 4; mi++) {
                int row = wm * 64 + mi * 16 + l7 + (lane & 8);
                int kc  = kk + ((lane & 16) >> 1);
                uint32_t off = (uint32_t)(row * PK + kc) * 2u;
                uint32_t ah0, ah1, ah2, ah3, al0, al1, al2, al3;
                ldm_x4(ah0, ah1, ah2, ah3, A_h + off);
                ldm_x4(al0, al1, al2, al3, A_l + off);
                #pragma unroll
                for (int ni = 0; ni < 8; ni++) {
                    float* d = acc[mi][ni];
                    mma_f16(d[0], d[1], d[2], d[3], ah0, ah1, ah2, ah3, bh[ni][0], bh[ni][1]);
                    mma_f16(d[0], d[1], d[2], d[3], ah0, ah1, ah2, ah3, bl[ni][0], bl[ni][1]);
                    mma_f16(d[0], d[1], d[2], d[3], al0, al1, al2, al3, bh[ni][0], bh[ni][1]);
                }
            }
        }
    }

    // --- epilogue ---
    const float* bias = b0p;
    float* Cd = C;
    int csub = 0, Nw = N;
    if (EPI == EPI_QKV) {
        int sel = n0 >> 10;
        bias = (sel == 0) ? b0p : (sel == 1) ? b1p : b2p;
        Cd = C + (long)sel * BT * Dm;
        csub = sel << 10;
        Nw = Dm;
    }

    #pragma unroll
    for (int mi = 0; mi < 4; mi++) {
        int r0 = m0 + wm * 64 + mi * 16 + g;
        #pragma unroll
        for (int ni = 0; ni < 8; ni++) {
            int cc = n0 + wn * 64 + ni * 8 + 2 * t;
            float b0v = bias ? bias[cc - csub] : 0.f;
            float b1v = bias ? bias[cc - csub + 1] : 0.f;
            float v0 = acc[mi][ni][0] + b0v, v1 = acc[mi][ni][1] + b1v;
            float v2 = acc[mi][ni][2] + b0v, v3 = acc[mi][ni][3] + b1v;
            long i0 = (long)r0 * Nw + (cc - csub);
            long i1 = (long)(r0 + 8) * Nw + (cc - csub);
            if (EPI == EPI_ADD) {
                v0 += res[i0]; v1 += res[i0 + 1];
                v2 += res[i1]; v3 += res[i1 + 1];
            }
            if (EPI == EPI_GELU) {
                v0 = 0.5f * v0 * (1.f + erff(v0 * 0.70710678118654752f));
                v1 = 0.5f * v1 * (1.f + erff(v1 * 0.70710678118654752f));
                v2 = 0.5f * v2 * (1.f + erff(v2 * 0.70710678118654752f));
                v3 = 0.5f * v3 * (1.f + erff(v3 * 0.70710678118654752f));
                __half h0, h1, h2, h3, l0, l1, l2, l3;
                split16(v0, h0, l0); split16(v1, h1, l1);
                split16(v2, h2, l2); split16(v3, h3, l3);
                *(__half2*)(Ch + i0) = __halves2half2(h0, h1);
                *(__half2*)(Ch + i1) = __halves2half2(h2, h3);
                *(__half2*)(Cl + i0) = __halves2half2(l0, l1);
                *(__half2*)(Cl + i1) = __halves2half2(l2, l3);
            } else {
                *(float2*)(Cd + i0) = make_float2(v0, v1);
                *(float2*)(Cd + i1) = make_float2(v2, v3);
            }
        }
    }
}

// ---------------------------------------------------------------------------
// Flash attention (fp32, causal) -> f16 hi/lo pair output
// ---------------------------------------------------------------------------
#define APAD 68
#define ATT_SMEM_FLOATS (4 * 64 * APAD)

__global__ __launch_bounds__(256) void attn_kernel(
    const float* __restrict__ Q, const float* __restrict__ K,
    const float* __restrict__ V, __half* __restrict__ Yh, __half* __restrict__ Yl)
{
    extern __shared__ float smem[];
    float (*Qs)[APAD]  = (float (*)[APAD])(smem);
    float (*Kst)[APAD] = (float (*)[APAD])(smem + 64 * APAD);
    float (*Vs)[APAD]  = (float (*)[APAD])(smem + 2 * 64 * APAD);
    float (*Ps)[APAD]  = (float (*)[APAD])(smem + 3 * 64 * APAD);

    const int qt = blockIdx.x, h = blockIdx.y, b = blockIdx.z;
    const int tid = threadIdx.x;
    const int tx = tid & 15;
    const int ty = tid >> 4;

    const long baseq = ((long)(b * Tq + qt * 64)) * Dm + h * HD;

    for (int i = tid; i < 64 * 16; i += 256) {
        int r = i >> 4, c4 = (i & 15) << 2;
        float4 v = *(const float4*)(Q + baseq + (long)r * Dm + c4);
        Qs[r][c4] = v.x; Qs[r][c4 + 1] = v.y; Qs[r][c4 + 2] = v.z; Qs[r][c4 + 3] = v.w;
    }

    float m_i[4], l_i[4], o[4][4];
    #pragma unroll
    for (int i = 0; i < 4; i++) {
        m_i[i] = -1e30f; l_i[i] = 0.f;
        #pragma unroll
        for (int j = 0; j < 4; j++) o[i][j] = 0.f;
    }

    for (int kt = 0; kt <= qt; kt++) {
        const long basek = ((long)(b * Tq + kt * 64)) * Dm + h * HD;
        for (int i = tid; i < 64 * 16; i += 256) {
            int r = i >> 4, c4 = (i & 15) << 2;
            float4 kv = *(const float4*)(K + basek + (long)r * Dm + c4);
            Kst[c4][r] = kv.x; Kst[c4 + 1][r] = kv.y; Kst[c4 + 2][r] = kv.z; Kst[c4 + 3][r] = kv.w;
            float4 vv = *(const float4*)(V + basek + (long)r * Dm + c4);
            Vs[r][c4] = vv.x; Vs[r][c4 + 1] = vv.y; Vs[r][c4 + 2] = vv.z; Vs[r][c4 + 3] = vv.w;
        }
        __syncthreads();

        float s[4][4];
        #pragma unroll
        for (int i = 0; i < 4; i++)
            #pragma unroll
            for (int j = 0; j < 4; j++) s[i][j] = 0.f;

        #pragma unroll 8
        for (int kk = 0; kk < 64; kk++) {
            float a0 = Qs[4 * ty + 0][kk];
            float a1 = Qs[4 * ty + 1][kk];
            float a2 = Qs[4 * ty + 2][kk];
            float a3 = Qs[4 * ty + 3][kk];
            float4 bb = *(const float4*)&Kst[kk][4 * tx];
            s[0][0] = fmaf(a0, bb.x, s[0][0]); s[0][1] = fmaf(a0, bb.y, s[0][1]);
            s[0][2] = fmaf(a0, bb.z, s[0][2]); s[0][3] = fmaf(a0, bb.w, s[0][3]);
            s[1][0] = fmaf(a1, bb.x, s[1][0]); s[1][1] = fmaf(a1, bb.y, s[1][1]);
            s[1][2] = fmaf(a1, bb.z, s[1][2]); s[1][3] = fmaf(a1, bb.w, s[1][3]);
            s[2][0] = fmaf(a2, bb.x, s[2][0]); s[2][1] = fmaf(a2, bb.y, s[2][1]);
            s[2][2] = fmaf(a2, bb.z, s[2][2]); s[2][3] = fmaf(a2, bb.w, s[2][3]);
            s[3][0] = fmaf(a3, bb.x, s[3][0]); s[3][1] = fmaf(a3, bb.y, s[3][1]);
            s[3][2] = fmaf(a3, bb.z, s[3][2]); s[3][3] = fmaf(a3, bb.w, s[3][3]);
        }

        const float scale = 0.125f;
        #pragma unroll
        for (int i = 0; i < 4; i++)
            #pragma unroll
            for (int j = 0; j < 4; j++) s[i][j] *= scale;

        if (kt == qt) {
            #pragma unroll
            for (int i = 0; i < 4; i++)
                #pragma unroll
                for (int j = 0; j < 4; j++)
                    if (4 * tx + j > 4 * ty + i) s[i][j] = -1e30f;
        }

        #pragma unroll
        for (int i = 0; i < 4; i++) {
            float rmax = fmaxf(fmaxf(s[i][0], s[i][1]), fmaxf(s[i][2], s[i][3]));
            #pragma unroll
            for (int m = 8; m; m >>= 1)
                rmax = fmaxf(rmax, __shfl_xor_sync(0xffffffffu, rmax, m));
            float mnew  = fmaxf(m_i[i], rmax);
            float alpha = expf(m_i[i] - mnew);
            m_i[i] = mnew;
            float rsum = 0.f;
            #pragma unroll
            for (int j = 0; j < 4; j++) {
                float p = expf(s[i][j] - mnew);
                s[i][j] = p;
                rsum += p;
            }
            #pragma unroll
            for (int m = 8; m; m >>= 1)
                rsum += __shfl_xor_sync(0xffffffffu, rsum, m);
            l_i[i] = l_i[i] * alpha + rsum;
            #pragma unroll
            for (int j = 0; j < 4; j++) o[i][j] *= alpha;
        }

        #pragma unroll
        for (int i = 0; i < 4; i++)
            #pragma unroll
            for (int j = 0; j < 4; j++)
                Ps[4 * ty + i][4 * tx + j] = s[i][j];
        __syncthreads();

        #pragma unroll 8
        for (int kk = 0; kk < 64; kk++) {
            float a0 = Ps[4 * ty + 0][kk];
            float a1 = Ps[4 * ty + 1][kk];
            float a2 = Ps[4 * ty + 2][kk];
            float a3 = Ps[4 * ty + 3][kk];
            float4 bb = *(const float4*)&Vs[kk][4 * tx];
            o[0][0] = fmaf(a0, bb.x, o[0][0]); o[0][1] = fmaf(a0, bb.y, o[0][1]);
            o[0][2] = fmaf(a0, bb.z, o[0][2]); o[0][3] = fmaf(a0, bb.w, o[0][3]);
            o[1][0] = fmaf(a1, bb.x, o[1][0]); o[1][1] = fmaf(a1, bb.y, o[1][1]);
            o[1][2] = fmaf(a1, bb.z, o[1][2]); o[1][3] = fmaf(a1, bb.w, o[1][3]);
            o[2][0] = fmaf(a2, bb.x, o[2][0]); o[2][1] = fmaf(a2, bb.y, o[2][1]);
            o[2][2] = fmaf(a2, bb.z, o[2][2]); o[2][3] = fmaf(a2, bb.w, o[2][3]);
            o[3][0] = fmaf(a3, bb.x, o[3][0]); o[3][1] = fmaf(a3, bb.y, o[3][1]);
            o[3][2] = fmaf(a3, bb.z, o[3][2]); o[3][3] = fmaf(a3, bb.w, o[3][3]);
        }
        __syncthreads();
    }

    #pragma unroll
    for (int i = 0; i < 4; i++) {
        float inv = 1.f / l_i[i];
        long orow = baseq + (long)(4 * ty + i) * Dm + 4 * tx;
        #pragma unroll
        for (int j = 0; j < 4; j++) {
            float val = o[i][j] * inv;
            __half hi, lo;
            split16(val, hi, lo);
            Yh[orow + j] = hi;
            Yl[orow + j] = lo;
        }
    }
}

// ---------------------------------------------------------------------------
// Launcher  (launch order arranged so launch #6 = first QKV GEMM for ncu -s 5)
// ---------------------------------------------------------------------------
extern "C" void kernel_launch(void* const* d_in, const int* in_sizes, int n_in,
                              void* d_out, int out_size)
{
    const int*   idx  = (const int*)  d_in[0];
    const int*   ts   = (const int*)  d_in[1];
    const float* tok  = (const float*)d_in[2];
    const float* pos  = (const float*)d_in[3];
    const float* gpos = (const float*)d_in[4];
    const float* ln1w = (const float*)d_in[5];
    const float* ln1b = (const float*)d_in[6];
    const float* Wq   = (const float*)d_in[7];
    const float* bq   = (const float*)d_in[8];
    const float* Wk   = (const float*)d_in[9];
    const float* bk   = (const float*)d_in[10];
    const float* Wv   = (const float*)d_in[11];
    const float* bv   = (const float*)d_in[12];
    const float* Wo   = (const float*)d_in[13];
    const float* bo   = (const float*)d_in[14];
    const float* ln2w = (const float*)d_in[15];
    const float* ln2b = (const float*)d_in[16];
    const float* W1   = (const float*)d_in[17];
    const float* b1   = (const float*)d_in[18];
    const float* W2   = (const float*)d_in[19];
    const float* b2   = (const float*)d_in[20];
    const float* lnfw = (const float*)d_in[21];
    const float* lnfb = (const float*)d_in[22];
    const float* hw   = (const float*)d_in[23];
    float* out = (float*)d_out;

    float *x, *qkv;
    __half *pah, *pal, *pbh, *pbl, *wh, *wl;
    cudaGetSymbolAddress((void**)&x,   g_x);
    cudaGetSymbolAddress((void**)&qkv, g_qkv);
    cudaGetSymbolAddress((void**)&pah, g_pa_h);
    cudaGetSymbolAddress((void**)&pal, g_pa_l);
    cudaGetSymbolAddress((void**)&pbh, g_pb_h);
    cudaGetSymbolAddress((void**)&pbl, g_pb_l);
    cudaGetSymbolAddress((void**)&wh,  g_wh);
    cudaGetSymbolAddress((void**)&wl,  g_wl);

    cudaFuncSetAttribute(attn_kernel, cudaFuncAttributeMaxDynamicSharedMemorySize,
                         ATT_SMEM_FLOATS * (int)sizeof(float));
    cudaFuncSetAttribute(gemm_hmma<EPI_NONE>, cudaFuncAttributeMaxDynamicSharedMemorySize, GEMM_SMEM);
    cudaFuncSetAttribute(gemm_hmma<EPI_ADD>,  cudaFuncAttributeMaxDynamicSharedMemorySize, GEMM_SMEM);
    cudaFuncSetAttribute(gemm_hmma<EPI_GELU>, cudaFuncAttributeMaxDynamicSharedMemorySize, GEMM_SMEM);
    cudaFuncSetAttribute(gemm_hmma<EPI_QKV>,  cudaFuncAttributeMaxDynamicSharedMemorySize, GEMM_SMEM);

    auto cvt = [&](const float* src, long off, long n) {
        cvt_pair<<<(int)((n / 4 + 255) / 256), 256>>>(src, wh + off, wl + off, n);
    };

    const dim3 gD(Dm / 128, BT / 256);
    const dim3 gQKV(3 * Dm / 128, BT / 256);
    const dim3 g2D(2 * Dm / 128, BT / 256);
    const dim3 gV(Vv / 128, BT / 256);

    float* qb = qkv;
    float* kb = qkv + (long)BT * Dm;
    float* vb = qkv + 2L * BT * Dm;

    // #1..#5: embed, ln, cvtQ, cvtK, cvtV  -> #6 = QKV GEMM (ncu -s 5 -c 1)
    embed_kernel<<<(BT * Dm) / 256, 256>>>(idx, ts, tok, pos, gpos, x);
    layernorm_pair<<<BT, 256>>>(x, ln1w, ln1b, pah, pal);
    cvt(Wq, OFF_WQ, 8L * DD);
    cvt(Wk, OFF_WK, 8L * DD);
    cvt(Wv, OFF_WV, 8L * DD);

    bool cvted = false;

    for (int l = 0; l < Ll; l++) {
        if (l > 0)
            layernorm_pair<<<BT, 256>>>(x, ln1w + (long)l * Dm, ln1b + (long)l * Dm, pah, pal);

        gemm_hmma<EPI_QKV><<<gQKV, 256, GEMM_SMEM>>>(
            pah, pal, wh + OFF_WQ + (long)l * DD, wl + OFF_WQ + (long)l * DD,
            8L * DD,
            bq + (long)l * Dm, bk + (long)l * Dm, bv + (long)l * Dm,
            nullptr, qkv, nullptr, nullptr, BT, 3 * Dm, Dm);

        attn_kernel<<<dim3(Tq / 64, Hh, Bq), 256,
                      ATT_SMEM_FLOATS * sizeof(float)>>>(qb, kb, vb, pah, pal);

        if (!cvted) cvt(Wo, OFF_WO, 8L * DD);

        gemm_hmma<EPI_ADD><<<gD, 256, GEMM_SMEM>>>(
            pah, pal, wh + OFF_WO + (long)l * DD, wl + OFF_WO + (long)l * DD, 0,
            bo + (long)l * Dm, nullptr, nullptr, x, x, nullptr, nullptr, BT, Dm, Dm);

        layernorm_pair<<<BT, 256>>>(x, ln2w + (long)l * Dm, ln2b + (long)l * Dm, pah, pal);

        if (!cvted) cvt(W1, OFF_W1, 16L * DD);

        gemm_hmma<EPI_GELU><<<g2D, 256, GEMM_SMEM>>>(
            pah, pal, wh + OFF_W1 + (long)l * 2 * DD, wl + OFF_W1 + (long)l * 2 * DD, 0,
            b1 + (long)l * 2 * Dm, nullptr, nullptr, nullptr,
            nullptr, pbh, pbl, BT, 2 * Dm, Dm);

        if (!cvted) { cvt(W2, OFF_W2, 16L * DD); cvted = true; }

        gemm_hmma<EPI_ADD><<<gD, 256, GEMM_SMEM>>>(
            pbh, pbl, wh + OFF_W2 + (long)l * 2 * DD, wl + OFF_W2 + (long)l * 2 * DD, 0,
            b2 + (long)l * Dm, nullptr, nullptr, x, x, nullptr, nullptr, BT, Dm, 2 * Dm);
    }

    layernorm_pair<<<BT, 256>>>(x, lnfw, lnfb, pah, pal);
    cvt(hw, OFF_HW, 8L * DD);
    gemm_hmma<EPI_NONE><<<gV, 256, GEMM_SMEM>>>(
        pah, pal, wh + OFF_HW, wl + OFF_HW, 0,
        nullptr, nullptr, nullptr, nullptr, out, nullptr, nullptr, BT, Vv, Dm);
}

// round 7
// speedup vs baseline: 1.0724x; 1.0724x over previous
#include <cuda_runtime.h>
#include <cuda_fp16.h>
#include <math.h>
#include <stdint.h>

// ---------------------------------------------------------------------------
// Problem constants
// ---------------------------------------------------------------------------
#define Bq   8
#define Tq   1024
#define Dm   1024
#define Hh   16
#define Ll   8
#define Vv   8192
#define HD   64
#define BT   (Bq*Tq)

// ---------------------------------------------------------------------------
// Scratch (static device globals)
// ---------------------------------------------------------------------------
__device__ float g_x[BT * Dm];           // residual stream (f32)
__device__ float g_qkv[3L * BT * Dm];    // q | k | v

__device__ __half g_pa_h[BT * Dm];       // pair buf A: LN out / attn out
__device__ __half g_pa_l[BT * Dm];
__device__ __half g_pb_h[BT * 2 * Dm];   // pair buf B: MLP hidden
__device__ __half g_pb_l[BT * 2 * Dm];

#define DD      (Dm*Dm)
#define OFF_WQ  0L
#define OFF_WK  (8L*DD)
#define OFF_WV  (16L*DD)
#define OFF_WO  (24L*DD)
#define OFF_W1  (32L*DD)
#define OFF_W2  (48L*DD)
#define OFF_HW  (64L*DD)
#define WTOT    (72L*DD)
__device__ __half g_wh[WTOT];
__device__ __half g_wl[WTOT];

// ---------------------------------------------------------------------------
// Helpers
// ---------------------------------------------------------------------------
__device__ __forceinline__ uint32_t smem_u32(const void* p) {
    uint32_t a;
    asm("{ .reg .u64 t; cvta.to.shared.u64 t, %1; cvt.u32.u64 %0, t; }"
        : "=r"(a) : "l"(p));
    return a;
}
__device__ __forceinline__ void cpa16(uint32_t dst, const void* src) {
    asm volatile("cp.async.cg.shared.global [%0], [%1], 16;" :: "r"(dst), "l"(src));
}
__device__ __forceinline__ void ldm_x4(uint32_t& r0, uint32_t& r1,
                                       uint32_t& r2, uint32_t& r3, uint32_t addr) {
    asm volatile("ldmatrix.sync.aligned.m8n8.x4.shared.b16 {%0,%1,%2,%3}, [%4];"
                 : "=r"(r0), "=r"(r1), "=r"(r2), "=r"(r3) : "r"(addr));
}
// f32-accumulate HMMA (main term)
__device__ __forceinline__ void mma_f16(float& d0, float& d1, float& d2, float& d3,
                                        uint32_t a0, uint32_t a1, uint32_t a2, uint32_t a3,
                                        uint32_t b0, uint32_t b1) {
    asm volatile(
        "mma.sync.aligned.m16n8k16.row.col.f32.f16.f16.f32 "
        "{%0,%1,%2,%3}, {%4,%5,%6,%7}, {%8,%9}, {%0,%1,%2,%3};"
        : "+f"(d0), "+f"(d1), "+f"(d2), "+f"(d3)
        : "r"(a0), "r"(a1), "r"(a2), "r"(a3), "r"(b0), "r"(b1));
}
// f16-accumulate HMMA (correction terms; tests 2x-rate hypothesis)
__device__ __forceinline__ void mma_f16h(uint32_t& c0, uint32_t& c1,
                                         uint32_t a0, uint32_t a1, uint32_t a2, uint32_t a3,
                                         uint32_t b0, uint32_t b1) {
    asm volatile(
        "mma.sync.aligned.m16n8k16.row.col.f16.f16.f16.f16 "
        "{%0,%1}, {%2,%3,%4,%5}, {%6,%7}, {%0,%1};"
        : "+r"(c0), "+r"(c1)
        : "r"(a0), "r"(a1), "r"(a2), "r"(a3), "r"(b0), "r"(b1));
}
__device__ __forceinline__ void split16(float x, __half& hi, __half& lo) {
    hi = __float2half_rn(x);
    lo = __float2half_rn(x - __half2float(hi));
}

// ---------------------------------------------------------------------------
// Weight f32 -> f16 hi/lo pair conversion
// ---------------------------------------------------------------------------
__global__ __launch_bounds__(256) void cvt_pair(
    const float* __restrict__ s, __half* __restrict__ h,
    __half* __restrict__ l, long n)
{
    long i = ((long)blockIdx.x * 256 + threadIdx.x) * 4;
    if (i >= n) return;
    float4 v = *(const float4*)(s + i);
    __half h0, h1, h2, h3, l0, l1, l2, l3;
    split16(v.x, h0, l0); split16(v.y, h1, l1);
    split16(v.z, h2, l2); split16(v.w, h3, l3);
    *(__half2*)(h + i)     = __halves2half2(h0, h1);
    *(__half2*)(h + i + 2) = __halves2half2(h2, h3);
    *(__half2*)(l + i)     = __halves2half2(l0, l1);
    *(__half2*)(l + i + 2) = __halves2half2(l2, l3);
}

// ---------------------------------------------------------------------------
// Embedding
// ---------------------------------------------------------------------------
__global__ __launch_bounds__(256) void embed_kernel(
    const int* __restrict__ idx, const int* __restrict__ ts,
    const float* __restrict__ tok, const float* __restrict__ pos,
    const float* __restrict__ gpos, float* __restrict__ x)
{
    long i = (long)blockIdx.x * 256 + threadIdx.x;
    int d = (int)(i % Dm);
    long bt = i / Dm;
    int t = (int)(bt % Tq);
    int b = (int)(bt / Tq);
    int tokid = idx[b * Tq + t];
    int tstep = ts[b];
    x[i] = tok[(long)tokid * Dm + d] + gpos[(long)tstep * Dm + d] + pos[(long)t * Dm + d];
}

// ---------------------------------------------------------------------------
// LayerNorm -> f16 hi/lo pair output
// ---------------------------------------------------------------------------
__global__ __launch_bounds__(256) void layernorm_pair(
    const float* __restrict__ X, const float* __restrict__ w,
    const float* __restrict__ b, __half* __restrict__ Yh, __half* __restrict__ Yl)
{
    int row = blockIdx.x;
    const float* x = X + (long)row * Dm;
    int tid = threadIdx.x;

    int i = tid * 4;
    float4 v = *(const float4*)(x + i);
    float s  = v.x + v.y + v.z + v.w;
    float ss = v.x*v.x + v.y*v.y + v.z*v.z + v.w*v.w;

    __shared__ float rs[8], rss[8];
    #pragma unroll
    for (int m = 16; m; m >>= 1) {
        s  += __shfl_xor_sync(0xffffffffu, s,  m);
        ss += __shfl_xor_sync(0xffffffffu, ss, m);
    }
    int wid = tid >> 5, lane = tid & 31;
    if (lane == 0) { rs[wid] = s; rss[wid] = ss; }
    __syncthreads();
    if (wid == 0) {
        s  = (lane < 8) ? rs[lane]  : 0.f;
        ss = (lane < 8) ? rss[lane] : 0.f;
        #pragma unroll
        for (int m = 4; m; m >>= 1) {
            s  += __shfl_xor_sync(0xffffffffu, s,  m);
            ss += __shfl_xor_sync(0xffffffffu, ss, m);
        }
        if (lane == 0) { rs[0] = s; rss[0] = ss; }
    }
    __syncthreads();
    float mean = rs[0] * (1.0f / Dm);
    float var  = rss[0] * (1.0f / Dm) - mean * mean;
    float rstd = rsqrtf(var + 1e-5f);

    float4 wv = *(const float4*)(w + i);
    float4 bv = *(const float4*)(b + i);
    float o0 = (v.x - mean) * rstd * wv.x + bv.x;
    float o1 = (v.y - mean) * rstd * wv.y + bv.y;
    float o2 = (v.z - mean) * rstd * wv.z + bv.z;
    float o3 = (v.w - mean) * rstd * wv.w + bv.w;

    long base = (long)row * Dm + i;
    __half h0, h1, h2, h3, l0, l1, l2, l3;
    split16(o0, h0, l0); split16(o1, h1, l1);
    split16(o2, h2, l2); split16(o3, h3, l3);
    *(__half2*)(Yh + base)     = __halves2half2(h0, h1);
    *(__half2*)(Yh + base + 2) = __halves2half2(h2, h3);
    *(__half2*)(Yl + base)     = __halves2half2(l0, l1);
    *(__half2*)(Yl + base + 2) = __halves2half2(l2, l3);
}

// ---------------------------------------------------------------------------
// HMMA GEMM (3x f16 split; corrections in f16 accumulators).
// CTA 128x128, k-step 32, cp.async double buffer, 8 warps of 64x32.
// ---------------------------------------------------------------------------
#define EPI_NONE 0
#define EPI_ADD  1
#define EPI_GELU 2
#define EPI_QKV  3

#define PK      40
#define TILE_H  (128*PK)
#define STG_H   (4*TILE_H)
#define GEMM_SMEM (2*STG_H*2)

template<int EPI>
__global__ __launch_bounds__(256, 2) void gemm_hmma(
    const __half* __restrict__ Ah, const __half* __restrict__ Al,
    const __half* __restrict__ Bh, const __half* __restrict__ Bl,
    long bStride,
    const float* __restrict__ b0p, const float* __restrict__ b1p,
    const float* __restrict__ b2p, const float* __restrict__ res,
    float* __restrict__ C, __half* __restrict__ Ch, __half* __restrict__ Cl,
    int M, int N, int K)
{
    extern __shared__ __align__(16) __half gsm[];
    const uint32_t sbase = smem_u32(gsm);

    const int tid = threadIdx.x, lane = tid & 31, warp = tid >> 5;
    const int g = lane >> 2, t = lane & 3, l7 = lane & 7;
    const int wm = warp & 1, wn = warp >> 1;
    const int m0 = blockIdx.y * 128, n0 = blockIdx.x * 128;

    float acc[4][4][4];          // main term, f32
    uint32_t corr[4][4][2];      // correction terms, packed f16x2
    #pragma unroll
    for (int a = 0; a < 4; a++)
        #pragma unroll
        for (int b = 0; b < 4; b++) {
            #pragma unroll
            for (int c = 0; c < 4; c++) acc[a][b][c] = 0.f;
            corr[a][b][0] = 0u; corr[a][b][1] = 0u;
        }

    const int S = K >> 5;

    auto issue = [&](int k0, int buf) {
        #pragma unroll
        for (int j = 0; j < 8; j++) {
            int c = tid + 256 * j;
            int tile = c >> 9;
            int r = (c >> 2) & 127;
            int q = c & 3;
            const __half* src;
            if (tile == 0)      src = Ah + (long)(m0 + r) * K + k0 + q * 8;
            else if (tile == 1) src = Al + (long)(m0 + r) * K + k0 + q * 8;
            else {
                long roff;
                if (EPI == EPI_QKV) {
                    int rg = n0 + r;
                    roff = (long)(rg >> 10) * bStride + (long)(rg & 1023) * K;
                } else {
                    roff = (long)(n0 + r) * K;
                }
                src = (tile == 2 ? Bh : Bl) + roff + k0 + q * 8;
            }
            uint32_t dst = sbase + (uint32_t)(buf * STG_H + tile * TILE_H + r * PK + q * 8) * 2u;
            cpa16(dst, src);
        }
        asm volatile("cp.async.commit_group;" ::: "memory");
    };

    issue(0, 0);

    for (int s = 0; s < S; s++) {
        asm volatile("cp.async.wait_group 0;" ::: "memory");
        __syncthreads();
        if (s + 1 < S) issue((s + 1) << 5, (s + 1) & 1);

        uint32_t sb  = sbase + (uint32_t)((s & 1) * STG_H) * 2u;
        uint32_t A_h = sb;
        uint32_t A_l = sb + TILE_H * 2u;
        uint32_t B_h = sb + 2u * TILE_H * 2u;
        uint32_t B_l = sb + 3u * TILE_H * 2u;

        #pragma unroll
        for (int kk = 0; kk < 32; kk += 16) {
            uint32_t bh[4][2], bl[4][2];
            #pragma unroll
            for (int p = 0; p < 2; p++) {
                int row = wn * 32 + p * 16 + l7 + ((lane & 16) >> 1);
                int kc  = kk + (lane & 8);
                uint32_t off = (uint32_t)(row * PK + kc) * 2u;
                ldm_x4(bh[2*p][0], bh[2*p][1], bh[2*p+1][0], bh[2*p+1][1], B_h + off);
                ldm_x4(bl[2*p][0], bl[2*p][1], bl[2*p+1][0], bl[2*p+1][1], B_l + off);
            }
            #pragma unroll
            for (int mi = 0; mi < 4; mi++) {
                int row = wm * 64 + mi * 16 + l7 + (lane & 8);
                int kc  = kk + ((lane & 16) >> 1);
                uint32_t off = (uint32_t)(row * PK + kc) * 2u;
                uint32_t ah0, ah1, ah2, ah3, al0, al1, al2, al3;
                ldm_x4(ah0, ah1, ah2, ah3, A_h + off);
                ldm_x4(al0, al1, al2, al3, A_l + off);
                #pragma unroll
                for (int ni = 0; ni < 4; ni++) {
                    float* d = acc[mi][ni];
                    uint32_t* c = corr[mi][ni];
                    mma_f16(d[0], d[1], d[2], d[3], ah0, ah1, ah2, ah3, bh[ni][0], bh[ni][1]);
                    mma_f16h(c[0], c[1], ah0, ah1, ah2, ah3, bl[ni][0], bl[ni][1]);
                    mma_f16h(c[0], c[1], al0, al1, al2, al3, bh[ni][0], bh[ni][1]);
                }
            }
        }
    }

    // --- epilogue ---
    const float* bias = b0p;
    float* Cd = C;
    int csub = 0, Nw = N;
    if (EPI == EPI_QKV) {
        int sel = n0 >> 10;
        bias = (sel == 0) ? b0p : (sel == 1) ? b1p : b2p;
        Cd = C + (long)sel * BT * Dm;
        csub = sel << 10;
        Nw = Dm;
    }

    #pragma unroll
    for (int mi = 0; mi < 4; mi++) {
        int r0 = m0 + wm * 64 + mi * 16 + g;
        #pragma unroll
        for (int ni = 0; ni < 4; ni++) {
            int cc = n0 + wn * 32 + ni * 8 + 2 * t;
            __half2 c0 = *(__half2*)&corr[mi][ni][0];
            __half2 c1 = *(__half2*)&corr[mi][ni][1];
            float b0v = bias ? bias[cc - csub] : 0.f;
            float b1v = bias ? bias[cc - csub + 1] : 0.f;
            float v0 = acc[mi][ni][0] + __low2float(c0)  + b0v;
            float v1 = acc[mi][ni][1] + __high2float(c0) + b1v;
            float v2 = acc[mi][ni][2] + __low2float(c1)  + b0v;
            float v3 = acc[mi][ni][3] + __high2float(c1) + b1v;
            long i0 = (long)r0 * Nw + (cc - csub);
            long i1 = (long)(r0 + 8) * Nw + (cc - csub);
            if (EPI == EPI_ADD) {
                v0 += res[i0]; v1 += res[i0 + 1];
                v2 += res[i1]; v3 += res[i1 + 1];
            }
            if (EPI == EPI_GELU) {
                v0 = 0.5f * v0 * (1.f + erff(v0 * 0.70710678118654752f));
                v1 = 0.5f * v1 * (1.f + erff(v1 * 0.70710678118654752f));
                v2 = 0.5f * v2 * (1.f + erff(v2 * 0.70710678118654752f));
                v3 = 0.5f * v3 * (1.f + erff(v3 * 0.70710678118654752f));
                __half h0, h1, h2, h3, l0, l1, l2, l3;
                split16(v0, h0, l0); split16(v1, h1, l1);
                split16(v2, h2, l2); split16(v3, h3, l3);
                *(__half2*)(Ch + i0) = __halves2half2(h0, h1);
                *(__half2*)(Ch + i1) = __halves2half2(h2, h3);
                *(__half2*)(Cl + i0) = __halves2half2(l0, l1);
                *(__half2*)(Cl + i1) = __halves2half2(l2, l3);
            } else {
                *(float2*)(Cd + i0) = make_float2(v0, v1);
                *(float2*)(Cd + i1) = make_float2(v2, v3);
            }
        }
    }
}

// ---------------------------------------------------------------------------
// Flash attention (fp32, causal) -> f16 hi/lo pair output
// ---------------------------------------------------------------------------
#define APAD 68
#define ATT_SMEM_FLOATS (4 * 64 * APAD)

__global__ __launch_bounds__(256) void attn_kernel(
    const float* __restrict__ Q, const float* __restrict__ K,
    const float* __restrict__ V, __half* __restrict__ Yh, __half* __restrict__ Yl)
{
    extern __shared__ float smem[];
    float (*Qs)[APAD]  = (float (*)[APAD])(smem);
    float (*Kst)[APAD] = (float (*)[APAD])(smem + 64 * APAD);
    float (*Vs)[APAD]  = (float (*)[APAD])(smem + 2 * 64 * APAD);
    float (*Ps)[APAD]  = (float (*)[APAD])(smem + 3 * 64 * APAD);

    const int qt = blockIdx.x, h = blockIdx.y, b = blockIdx.z;
    const int tid = threadIdx.x;
    const int tx = tid & 15;
    const int ty = tid >> 4;

    const long baseq = ((long)(b * Tq + qt * 64)) * Dm + h * HD;

    for (int i = tid; i < 64 * 16; i += 256) {
        int r = i >> 4, c4 = (i & 15) << 2;
        float4 v = *(const float4*)(Q + baseq + (long)r * Dm + c4);
        Qs[r][c4] = v.x; Qs[r][c4 + 1] = v.y; Qs[r][c4 + 2] = v.z; Qs[r][c4 + 3] = v.w;
    }

    float m_i[4], l_i[4], o[4][4];
    #pragma unroll
    for (int i = 0; i < 4; i++) {
        m_i[i] = -1e30f; l_i[i] = 0.f;
        #pragma unroll
        for (int j = 0; j < 4; j++) o[i][j] = 0.f;
    }

    for (int kt = 0; kt <= qt; kt++) {
        const long basek = ((long)(b * Tq + kt * 64)) * Dm + h * HD;
        for (int i = tid; i < 64 * 16; i += 256) {
            int r = i >> 4, c4 = (i & 15) << 2;
            float4 kv = *(const float4*)(K + basek + (long)r * Dm + c4);
            Kst[c4][r] = kv.x; Kst[c4 + 1][r] = kv.y; Kst[c4 + 2][r] = kv.z; Kst[c4 + 3][r] = kv.w;
            float4 vv = *(const float4*)(V + basek + (long)r * Dm + c4);
            Vs[r][c4] = vv.x; Vs[r][c4 + 1] = vv.y; Vs[r][c4 + 2] = vv.z; Vs[r][c4 + 3] = vv.w;
        }
        __syncthreads();

        float s[4][4];
        #pragma unroll
        for (int i = 0; i < 4; i++)
            #pragma unroll
            for (int j = 0; j < 4; j++) s[i][j] = 0.f;

        #pragma unroll 8
        for (int kk = 0; kk < 64; kk++) {
            float a0 = Qs[4 * ty + 0][kk];
            float a1 = Qs[4 * ty + 1][kk];
            float a2 = Qs[4 * ty + 2][kk];
            float a3 = Qs[4 * ty + 3][kk];
            float4 bb = *(const float4*)&Kst[kk][4 * tx];
            s[0][0] = fmaf(a0, bb.x, s[0][0]); s[0][1] = fmaf(a0, bb.y, s[0][1]);
            s[0][2] = fmaf(a0, bb.z, s[0][2]); s[0][3] = fmaf(a0, bb.w, s[0][3]);
            s[1][0] = fmaf(a1, bb.x, s[1][0]); s[1][1] = fmaf(a1, bb.y, s[1][1]);
            s[1][2] = fmaf(a1, bb.z, s[1][2]); s[1][3] = fmaf(a1, bb.w, s[1][3]);
            s[2][0] = fmaf(a2, bb.x, s[2][0]); s[2][1] = fmaf(a2, bb.y, s[2][1]);
            s[2][2] = fmaf(a2, bb.z, s[2][2]); s[2][3] = fmaf(a2, bb.w, s[2][3]);
            s[3][0] = fmaf(a3, bb.x, s[3][0]); s[3][1] = fmaf(a3, bb.y, s[3][1]);
            s[3][2] = fmaf(a3, bb.z, s[3][2]); s[3][3] = fmaf(a3, bb.w, s[3][3]);
        }

        const float scale = 0.125f;
        #pragma unroll
        for (int i = 0; i < 4; i++)
            #pragma unroll
            for (int j = 0; j < 4; j++) s[i][j] *= scale;

        if (kt == qt) {
            #pragma unroll
            for (int i = 0; i < 4; i++)
                #pragma unroll
                for (int j = 0; j < 4; j++)
                    if (4 * tx + j > 4 * ty + i) s[i][j] = -1e30f;
        }

        #pragma unroll
        for (int i = 0; i < 4; i++) {
            float rmax = fmaxf(fmaxf(s[i][0], s[i][1]), fmaxf(s[i][2], s[i][3]));
            #pragma unroll
            for (int m = 8; m; m >>= 1)
                rmax = fmaxf(rmax, __shfl_xor_sync(0xffffffffu, rmax, m));
            float mnew  = fmaxf(m_i[i], rmax);
            float alpha = expf(m_i[i] - mnew);
            m_i[i] = mnew;
            float rsum = 0.f;
            #pragma unroll
            for (int j = 0; j < 4; j++) {
                float p = expf(s[i][j] - mnew);
                s[i][j] = p;
                rsum += p;
            }
            #pragma unroll
            for (int m = 8; m; m >>= 1)
                rsum += __shfl_xor_sync(0xffffffffu, rsum, m);
            l_i[i] = l_i[i] * alpha + rsum;
            #pragma unroll
            for (int j = 0; j < 4; j++) o[i][j] *= alpha;
        }

        #pragma unroll
        for (int i = 0; i < 4; i++)
            #pragma unroll
            for (int j = 0; j < 4; j++)
                Ps[4 * ty + i][4 * tx + j] = s[i][j];
        __syncthreads();

        #pragma unroll 8
        for (int kk = 0; kk < 64; kk++) {
            float a0 = Ps[4 * ty + 0][kk];
            float a1 = Ps[4 * ty + 1][kk];
            float a2 = Ps[4 * ty + 2][kk];
            float a3 = Ps[4 * ty + 3][kk];
            float4 bb = *(const float4*)&Vs[kk][4 * tx];
            o[0][0] = fmaf(a0, bb.x, o[0][0]); o[0][1] = fmaf(a0, bb.y, o[0][1]);
            o[0][2] = fmaf(a0, bb.z, o[0][2]); o[0][3] = fmaf(a0, bb.w, o[0][3]);
            o[1][0] = fmaf(a1, bb.x, o[1][0]); o[1][1] = fmaf(a1, bb.y, o[1][1]);
            o[1][2] = fmaf(a1, bb.z, o[1][2]); o[1][3] = fmaf(a1, bb.w, o[1][3]);
            o[2][0] = fmaf(a2, bb.x, o[2][0]); o[2][1] = fmaf(a2, bb.y, o[2][1]);
            o[2][2] = fmaf(a2, bb.z, o[2][2]); o[2][3] = fmaf(a2, bb.w, o[2][3]);
            o[3][0] = fmaf(a3, bb.x, o[3][0]); o[3][1] = fmaf(a3, bb.y, o[3][1]);
            o[3][2] = fmaf(a3, bb.z, o[3][2]); o[3][3] = fmaf(a3, bb.w, o[3][3]);
        }
        __syncthreads();
    }

    #pragma unroll
    for (int i = 0; i < 4; i++) {
        float inv = 1.f / l_i[i];
        long orow = baseq + (long)(4 * ty + i) * Dm + 4 * tx;
        #pragma unroll
        for (int j = 0; j < 4; j++) {
            float val = o[i][j] * inv;
            __half hi, lo;
            split16(val, hi, lo);
            Yh[orow + j] = hi;
            Yl[orow + j] = lo;
        }
    }
}

// ---------------------------------------------------------------------------
// Launcher
// ---------------------------------------------------------------------------
extern "C" void kernel_launch(void* const* d_in, const int* in_sizes, int n_in,
                              void* d_out, int out_size)
{
    const int*   idx  = (const int*)  d_in[0];
    const int*   ts   = (const int*)  d_in[1];
    const float* tok  = (const float*)d_in[2];
    const float* pos  = (const float*)d_in[3];
    const float* gpos = (const float*)d_in[4];
    const float* ln1w = (const float*)d_in[5];
    const float* ln1b = (const float*)d_in[6];
    const float* Wq   = (const float*)d_in[7];
    const float* bq   = (const float*)d_in[8];
    const float* Wk   = (const float*)d_in[9];
    const float* bk   = (const float*)d_in[10];
    const float* Wv   = (const float*)d_in[11];
    const float* bv   = (const float*)d_in[12];
    const float* Wo   = (const float*)d_in[13];
    const float* bo   = (const float*)d_in[14];
    const float* ln2w = (const float*)d_in[15];
    const float* ln2b = (const float*)d_in[16];
    const float* W1   = (const float*)d_in[17];
    const float* b1   = (const float*)d_in[18];
    const float* W2   = (const float*)d_in[19];
    const float* b2   = (const float*)d_in[20];
    const float* lnfw = (const float*)d_in[21];
    const float* lnfb = (const float*)d_in[22];
    const float* hw   = (const float*)d_in[23];
    float* out = (float*)d_out;

    float *x, *qkv;
    __half *pah, *pal, *pbh, *pbl, *wh, *wl;
    cudaGetSymbolAddress((void**)&x,   g_x);
    cudaGetSymbolAddress((void**)&qkv, g_qkv);
    cudaGetSymbolAddress((void**)&pah, g_pa_h);
    cudaGetSymbolAddress((void**)&pal, g_pa_l);
    cudaGetSymbolAddress((void**)&pbh, g_pb_h);
    cudaGetSymbolAddress((void**)&pbl, g_pb_l);
    cudaGetSymbolAddress((void**)&wh,  g_wh);
    cudaGetSymbolAddress((void**)&wl,  g_wl);

    cudaFuncSetAttribute(attn_kernel, cudaFuncAttributeMaxDynamicSharedMemorySize,
                         ATT_SMEM_FLOATS * (int)sizeof(float));
    cudaFuncSetAttribute(gemm_hmma<EPI_NONE>, cudaFuncAttributeMaxDynamicSharedMemorySize, GEMM_SMEM);
    cudaFuncSetAttribute(gemm_hmma<EPI_ADD>,  cudaFuncAttributeMaxDynamicSharedMemorySize, GEMM_SMEM);
    cudaFuncSetAttribute(gemm_hmma<EPI_GELU>, cudaFuncAttributeMaxDynamicSharedMemorySize, GEMM_SMEM);
    cudaFuncSetAttribute(gemm_hmma<EPI_QKV>,  cudaFuncAttributeMaxDynamicSharedMemorySize, GEMM_SMEM);

    auto cvt = [&](const float* src, long off, long n) {
        cvt_pair<<<(int)((n / 4 + 255) / 256), 256>>>(src, wh + off, wl + off, n);
    };
    cvt(Wq, OFF_WQ, 8L * DD);
    cvt(Wk, OFF_WK, 8L * DD);
    cvt(Wv, OFF_WV, 8L * DD);
    cvt(Wo, OFF_WO, 8L * DD);
    cvt(W1, OFF_W1, 16L * DD);
    cvt(W2, OFF_W2, 16L * DD);
    cvt(hw, OFF_HW, 8L * DD);

    embed_kernel<<<(BT * Dm) / 256, 256>>>(idx, ts, tok, pos, gpos, x);

    const dim3 gD(Dm / 128, BT / 128);
    const dim3 gQKV(3 * Dm / 128, BT / 128);
    const dim3 g2D(2 * Dm / 128, BT / 128);
    const dim3 gV(Vv / 128, BT / 128);

    float* qb = qkv;
    float* kb = qkv + (long)BT * Dm;
    float* vb = qkv + 2L * BT * Dm;

    for (int l = 0; l < Ll; l++) {
        layernorm_pair<<<BT, 256>>>(x, ln1w + (long)l * Dm, ln1b + (long)l * Dm, pah, pal);

        gemm_hmma<EPI_QKV><<<gQKV, 256, GEMM_SMEM>>>(
            pah, pal, wh + OFF_WQ + (long)l * DD, wl + OFF_WQ + (long)l * DD,
            8L * DD,
            bq + (long)l * Dm, bk + (long)l * Dm, bv + (long)l * Dm,
            nullptr, qkv, nullptr, nullptr, BT, 3 * Dm, Dm);

        attn_kernel<<<dim3(Tq / 64, Hh, Bq), 256,
                      ATT_SMEM_FLOATS * sizeof(float)>>>(qb, kb, vb, pah, pal);

        gemm_hmma<EPI_ADD><<<gD, 256, GEMM_SMEM>>>(
            pah, pal, wh + OFF_WO + (long)l * DD, wl + OFF_WO + (long)l * DD, 0,
            bo + (long)l * Dm, nullptr, nullptr, x, x, nullptr, nullptr, BT, Dm, Dm);

        layernorm_pair<<<BT, 256>>>(x, ln2w + (long)l * Dm, ln2b + (long)l * Dm, pah, pal);

        gemm_hmma<EPI_GELU><<<g2D, 256, GEMM_SMEM>>>(
            pah, pal, wh + OFF_W1 + (long)l * 2 * DD, wl + OFF_W1 + (long)l * 2 * DD, 0,
            b1 + (long)l * 2 * Dm, nullptr, nullptr, nullptr,
            nullptr, pbh, pbl, BT, 2 * Dm, Dm);

        gemm_hmma<EPI_ADD><<<gD, 256, GEMM_SMEM>>>(
            pbh, pbl, wh + OFF_W2 + (long)l * 2 * DD, wl + OFF_W2 + (long)l * 2 * DD, 0,
            b2 + (long)l * Dm, nullptr, nullptr, x, x, nullptr, nullptr, BT, Dm, 2 * Dm);
    }

    layernorm_pair<<<BT, 256>>>(x, lnfw, lnfb, pah, pal);
    gemm_hmma<EPI_NONE><<<gV, 256, GEMM_SMEM>>>(
        pah, pal, wh + OFF_HW, wl + OFF_HW, 0,
        nullptr, nullptr, nullptr, nullptr, out, nullptr, nullptr, BT, Vv, Dm);
}